// round 3
// baseline (speedup 1.0000x reference)
#include <cuda_runtime.h>
#include <cstdint>

// Embedding gather: out[token, :] = embedding[input_ids[token], :]
// input_ids: [4096] int32, embedding: [32000, 1024] fp32, out: [4096, 1024] fp32
//
// One WARP per token. Each lane moves 8 float4 (lane + 32*i), giving 8
// independent in-flight LDG.128 per thread (MLP=8) to hide DRAM latency.
// CTA = 256 threads = 8 tokens; grid = 4096/8 = 512.

static constexpr int VEC_PER_ROW = 256;   // 1024 floats / 4
static constexpr int TOKENS_PER_CTA = 8;
static constexpr int VECS_PER_LANE = VEC_PER_ROW / 32;  // 8

__global__ void __launch_bounds__(256, 8)
embed_gather_kernel(const int* __restrict__ ids,
                    const float4* __restrict__ emb,
                    float4* __restrict__ out,
                    int n_tokens)
{
    int token = blockIdx.x * TOKENS_PER_CTA + (threadIdx.x >> 5);
    if (token >= n_tokens) return;
    int lane = threadIdx.x & 31;

    int id = ids[token];   // warp-uniform broadcast load
    const float4* __restrict__ src = emb + (size_t)id * VEC_PER_ROW;
    float4* __restrict__ dst = out + (size_t)token * VEC_PER_ROW;

    float4 v[VECS_PER_LANE];
    #pragma unroll
    for (int i = 0; i < VECS_PER_LANE; i++)
        v[i] = __ldg(&src[lane + i * 32]);   // 8 independent LDG.128
    #pragma unroll
    for (int i = 0; i < VECS_PER_LANE; i++)
        dst[lane + i * 32] = v[i];
}

extern "C" void kernel_launch(void* const* d_in, const int* in_sizes, int n_in,
                              void* d_out, int out_size)
{
    const int*    ids = (const int*)d_in[0];
    const float4* emb = (const float4*)d_in[1];
    float4*       out = (float4*)d_out;

    int n_tokens = in_sizes[0];   // 4096
    int grid = (n_tokens + TOKENS_PER_CTA - 1) / TOKENS_PER_CTA;  // 512
    embed_gather_kernel<<<grid, 256>>>(ids, emb, out, n_tokens);
}